// round 10
// baseline (speedup 1.0000x reference)
#include <cuda_runtime.h>
#include <cstdint>
#include <math.h>

#define B 96
#define N 512
#define M 512
#define D 32

#define THREADS 288          // warps 0..7 = producers (64 cols each), warp 8 = DTW
#define NPROD 8
#define RSLOTS 52            // ring: 32-row consumption window + 20-row lead
#define LEAD   (RSLOTS - 32) // 20
#define SLOT_F 640           // 32 * 20 floats (16 data + 4 pad) per row slot
#define TSTRIDE_F 20

#define OFF_S1    0                              // 512*32 = 16384 floats
#define OFF_RING  (512 * 32)                     // 52*640 = 33280 floats
#define OFF_SQ1   (OFF_RING + RSLOTS * SLOT_F)   // 512 floats
#define OFF_FLAGS (OFF_SQ1 + 512)                // 512 ints
#define OFF_PROG  (OFF_FLAGS + 512)
#define SMEM_FLOATS (OFF_PROG + 4)
#define SMEM_BYTES (SMEM_FLOATS * 4)             // 202,768 B (< 227KB cap)

// ---------------------------------------------------------------------------
// helpers
// ---------------------------------------------------------------------------
__device__ __forceinline__ unsigned long long pack2f(float x, float y) {
    unsigned long long r;
    asm("mov.b64 %0, {%1, %2};" : "=l"(r) : "f"(x), "f"(y));
    return r;
}
__device__ __forceinline__ void ffma2(unsigned long long& d,
                                      unsigned long long a, unsigned long long b) {
    asm("fma.rn.f32x2 %0, %1, %2, %0;" : "+l"(d) : "l"(a), "l"(b));
}
__device__ __forceinline__ void unpack2f(unsigned long long v, float& x, float& y) {
    asm("mov.b64 {%0, %1}, %2;" : "=f"(x), "=f"(y) : "l"(v));
}
__device__ __forceinline__ void lds_v2u64(unsigned saddr,
                                          unsigned long long& a, unsigned long long& b) {
    asm volatile("ld.shared.v2.u64 {%0, %1}, [%2];" : "=l"(a), "=l"(b) : "r"(saddr));
}
__device__ __forceinline__ void sts_v2f32(unsigned saddr, float a, float b) {
    asm volatile("st.shared.v2.f32 [%0], {%1, %2};" :: "r"(saddr), "f"(a), "f"(b) : "memory");
}
__device__ __forceinline__ float lds_f32(unsigned saddr) {
    float v;
    asm volatile("ld.shared.f32 %0, [%1];" : "=f"(v) : "r"(saddr));
    return v;
}
__device__ __forceinline__ float fast_sqrt(float x) {
    float r;
    asm("sqrt.approx.f32 %0, %1;" : "=f"(r) : "f"(x));
    return r;
}
__device__ __forceinline__ void cp_async16(unsigned dst, const float* src) {
    asm volatile("cp.async.cg.shared.global [%0], [%1], 16;\n"
                 :: "r"(dst), "l"(src) : "memory");
}
__device__ __forceinline__ int ld_acquire_s32(unsigned addr) {
    int v;
    asm volatile("ld.acquire.cta.shared.b32 %0, [%1];" : "=r"(v) : "r"(addr) : "memory");
    return v;
}
__device__ __forceinline__ void st_release_s32(unsigned addr, int v) {
    asm volatile("st.release.cta.shared.b32 [%0], %1;" :: "r"(addr), "r"(v) : "memory");
}
__device__ __forceinline__ void red_add_release(unsigned addr, unsigned v) {
    asm volatile("red.release.cta.shared.add.u32 [%0], %1;" :: "r"(addr), "r"(v) : "memory");
}

// ---------------------------------------------------------------------------
// Fused kernel: 1 CTA per batch. 8 producer warps each own 64 columns of
// seq2 held entirely in REGISTERS (2 cols/lane); per row they broadcast-read
// the staged seq1 row from smem (1-phase LDS), FFMA2 the dot products, and
// write their column slice into the ring. Consumer = warp 8 (hi-wid priority).
// Row readiness = per-row counter reaching 8 (red.release / ld.acquire).
// ---------------------------------------------------------------------------
__global__ __launch_bounds__(THREADS)
void fused_dtw(const float* __restrict__ seq1, const float* __restrict__ seq2,
               float* __restrict__ out)
{
    extern __shared__ float sm[];
    const int b = blockIdx.x;
    const int tid = threadIdx.x;
    const int wid = tid >> 5;
    const int lane = tid & 31;

    const unsigned smb   = (unsigned)__cvta_generic_to_shared(sm);
    const unsigned s1b   = smb + OFF_S1 * 4;
    const unsigned ringb = smb + OFF_RING * 4;
    const unsigned sq1b  = smb + OFF_SQ1 * 4;
    const unsigned flagb = smb + OFF_FLAGS * 4;
    const unsigned progb = smb + OFF_PROG * 4;

    // ---- stage seq1 (64KB) via cp.async; flags/prog init ----
    const float* s1g = seq1 + (size_t)b * N * D;
    for (int c = tid; c < 512 * 8; c += THREADS) {
        int row = c >> 3, q = c & 7;
        cp_async16(s1b + (unsigned)(row * 128 + q * 16), s1g + row * 32 + q * 4);
    }
    asm volatile("cp.async.commit_group;\n" ::: "memory");
    for (int i = tid; i < 512; i += THREADS) ((int*)(sm + OFF_FLAGS))[i] = 0;
    if (tid == 0) ((int*)(sm + OFF_PROG))[0] = -1;

    // ---- producers: pull own 2 seq2 columns into registers (gmem) ----
    unsigned long long s2a[16], s2b2[16];
    float sq2a = 0.f, sq2b = 0.f;
    if (wid < NPROD) {
        const int j0 = 64 * wid + 2 * lane;
        const float4* va = reinterpret_cast<const float4*>(seq2 + (size_t)b * M * D + (size_t)j0 * D);
        const float4* vb = reinterpret_cast<const float4*>(seq2 + (size_t)b * M * D + (size_t)(j0 + 1) * D);
#pragma unroll
        for (int q = 0; q < 8; ++q) {
            float4 x = va[q];
            s2a[2 * q] = pack2f(x.x, x.y); s2a[2 * q + 1] = pack2f(x.z, x.w);
            sq2a = fmaf(x.x, x.x, sq2a); sq2a = fmaf(x.y, x.y, sq2a);
            sq2a = fmaf(x.z, x.z, sq2a); sq2a = fmaf(x.w, x.w, sq2a);
        }
#pragma unroll
        for (int q = 0; q < 8; ++q) {
            float4 x = vb[q];
            s2b2[2 * q] = pack2f(x.x, x.y); s2b2[2 * q + 1] = pack2f(x.z, x.w);
            sq2b = fmaf(x.x, x.x, sq2b); sq2b = fmaf(x.y, x.y, sq2b);
            sq2b = fmaf(x.z, x.z, sq2b); sq2b = fmaf(x.w, x.w, sq2b);
        }
    }

    asm volatile("cp.async.wait_group 0;\n" ::: "memory");
    __syncthreads();

    // ---- sq1 for all rows (from staged s1) ----
    for (int jj = tid; jj < 512; jj += THREADS) {
        const float* rp = sm + OFF_S1 + jj * 32;
        float acc = 0.f;
#pragma unroll
        for (int k = 0; k < 32; ++k) acc = fmaf(rp[k], rp[k], acc);
        sm[OFF_SQ1 + jj] = acc;
    }
    __syncthreads();

    if (wid == NPROD) {
        // =================== CONSUMER: DTW wavefront ===================
        const int t = lane;
        const float INF = INFINITY;

        float vprev[16];
#pragma unroll
        for (int k = 0; k < 16; ++k) vprev[k] = INF;
        float diag0 = (t == 0) ? 0.f : INF;
        float lastv = INF;

        const int STEPS = N + 31;   // 543

        for (int s = 0; s < STEPS; ++s) {
            float left0 = __shfl_up_sync(0xffffffffu, lastv, 1);
            if (t == 0) left0 = INF;

            if (s < N) {
                if (ld_acquire_s32(flagb + (unsigned)s * 4) < NPROD) {
                    while (ld_acquire_s32(flagb + (unsigned)s * 4) < NPROD) __nanosleep(20);
                }
            }

            const int r = s - t;
            if (r >= 0 && r < N) {
                const float4* cp = reinterpret_cast<const float4*>(
                    sm + OFF_RING + (r % RSLOTS) * SLOT_F + t * TSTRIDE_F);
                float4 c0 = cp[0], c1 = cp[1], c2 = cp[2], c3 = cp[3];
                float c[16] = { c0.x, c0.y, c0.z, c0.w,
                                c1.x, c1.y, c1.z, c1.w,
                                c2.x, c2.y, c2.z, c2.w,
                                c3.x, c3.y, c3.z, c3.w };

                float P[16];
                P[0] = c[0];
#pragma unroll
                for (int k = 1; k < 16; ++k) P[k] = P[k - 1] + c[k];

                float w[16];
                {
                    float m0 = fminf(vprev[0], diag0);
                    w[0] = m0;                      // P[-1] = 0
#pragma unroll
                    for (int k = 1; k < 16; ++k) {
                        float mk = fminf(vprev[k], vprev[k - 1]);
                        w[k] = mk - P[k - 1];
                    }
                }
#pragma unroll
                for (int k = 1; k < 16; ++k) w[k] = fminf(w[k], w[k - 1]);
#pragma unroll
                for (int k = 0; k < 16; ++k)
                    vprev[k] = P[k] + fminf(left0, w[k]);

                lastv = vprev[15];
                diag0 = left0;
            }

            if (lane == 0) st_release_s32(progb, s);   // step s fully consumed
        }

        if (t == 31) out[b] = lastv;
    } else {
        // =================== PRODUCERS: register-resident seq2 ===================
        const int j0 = 64 * wid + 2 * lane;
        const unsigned soff = (unsigned)(((j0 >> 4) * TSTRIDE_F + (j0 & 15)) * 4);

#pragma unroll 1
        for (int r = 0; r < N; ++r) {
            if (r >= RSLOTS) {                    // ring-reuse gate
                if (ld_acquire_s32(progb) < r - LEAD) {
                    while (ld_acquire_s32(progb) < r - LEAD) __nanosleep(40);
                }
            }

            const unsigned srow = s1b + (unsigned)(r * 128);
            unsigned long long a[16];
#pragma unroll
            for (int q = 0; q < 8; ++q)           // broadcast: all lanes same addr
                lds_v2u64(srow + q * 16, a[2 * q], a[2 * q + 1]);

            unsigned long long x0 = 0ull, x1 = 0ull, y0 = 0ull, y1 = 0ull;
#pragma unroll
            for (int u = 0; u < 16; u += 2) {
                ffma2(x0, a[u],     s2a[u]);
                ffma2(x1, a[u + 1], s2a[u + 1]);
                ffma2(y0, a[u],     s2b2[u]);
                ffma2(y1, a[u + 1], s2b2[u + 1]);
            }

            float e0, e1, e2, e3, f0, f1, f2, f3;
            unpack2f(x0, e0, e1); unpack2f(x1, e2, e3);
            unpack2f(y0, f0, f1); unpack2f(y1, f2, f3);
            float dotA = (e0 + e1) + (e2 + e3);
            float dotB = (f0 + f1) + (f2 + f3);

            const float sq1r = lds_f32(sq1b + (unsigned)(r * 4));   // broadcast
            float ddA = sq1r + sq2a - 2.f * dotA;
            float ddB = sq1r + sq2b - 2.f * dotB;
            float vA = fast_sqrt(fmaxf(ddA, 1e-12f));
            float vB = fast_sqrt(fmaxf(ddB, 1e-12f));

            const unsigned slot = ringb + (unsigned)((r % RSLOTS) * SLOT_F * 4);
            sts_v2f32(slot + soff, vA, vB);

            __syncwarp();
            if (lane == 0) red_add_release(flagb + (unsigned)r * 4, 1u);
        }
    }
}

// ---------------------------------------------------------------------------
extern "C" void kernel_launch(void* const* d_in, const int* in_sizes, int n_in,
                              void* d_out, int out_size)
{
    const float* seq1 = (const float*)d_in[0];
    const float* seq2 = (const float*)d_in[1];
    float* out = (float*)d_out;

    cudaFuncSetAttribute(fused_dtw, cudaFuncAttributeMaxDynamicSharedMemorySize,
                         SMEM_BYTES);
    fused_dtw<<<B, THREADS, SMEM_BYTES>>>(seq1, seq2, out);
}

// round 11
// speedup vs baseline: 1.1150x; 1.1150x over previous
#include <cuda_runtime.h>
#include <cstdint>
#include <math.h>

#define B 96
#define N 512
#define M 512
#define D 32

#define THREADS 288          // w0..w7 producers (w4 idle), w8 = DTW consumer
#define RSLOTS 52
#define LEAD   (RSLOTS - 32) // 20
#define SLOT_F 640
#define TSTRIDE_F 20

#define OFF_S1    0                              // 512*32 = 16384 floats
#define OFF_RING  (512 * 32)                     // 52*640 = 33280
#define OFF_SQ1   (OFF_RING + RSLOTS * SLOT_F)   // 512
#define OFF_PW    (OFF_SQ1 + 512)                // 8 words, stride 8 floats
#define OFF_PROG  (OFF_PW + 64)
#define SMEM_FLOATS (OFF_PROG + 4)
#define SMEM_BYTES (SMEM_FLOATS * 4)             // ~201.0 KB

// ---------------------------------------------------------------------------
__device__ __forceinline__ unsigned long long pack2f(float x, float y) {
    unsigned long long r;
    asm("mov.b64 %0, {%1, %2};" : "=l"(r) : "f"(x), "f"(y));
    return r;
}
__device__ __forceinline__ void ffma2(unsigned long long& d,
                                      unsigned long long a, unsigned long long b) {
    asm("fma.rn.f32x2 %0, %1, %2, %0;" : "+l"(d) : "l"(a), "l"(b));
}
__device__ __forceinline__ void unpack2f(unsigned long long v, float& x, float& y) {
    asm("mov.b64 {%0, %1}, %2;" : "=f"(x), "=f"(y) : "l"(v));
}
__device__ __forceinline__ void lds_v2u64(unsigned saddr,
                                          unsigned long long& a, unsigned long long& b) {
    asm volatile("ld.shared.v2.u64 {%0, %1}, [%2];" : "=l"(a), "=l"(b) : "r"(saddr));
}
__device__ __forceinline__ void sts_f32(unsigned saddr, float v) {
    asm volatile("st.shared.f32 [%0], %1;" :: "r"(saddr), "f"(v) : "memory");
}
__device__ __forceinline__ float lds_f32(unsigned saddr) {
    float v;
    asm volatile("ld.shared.f32 %0, [%1];" : "=f"(v) : "r"(saddr));
    return v;
}
__device__ __forceinline__ float fast_sqrt(float x) {
    float r;
    asm("sqrt.approx.f32 %0, %1;" : "=f"(r) : "f"(x));
    return r;
}
__device__ __forceinline__ void cp_async16(unsigned dst, const float* src) {
    asm volatile("cp.async.cg.shared.global [%0], [%1], 16;\n"
                 :: "r"(dst), "l"(src) : "memory");
}
__device__ __forceinline__ int ld_acquire_s32(unsigned addr) {
    int v;
    asm volatile("ld.acquire.cta.shared.b32 %0, [%1];" : "=r"(v) : "r"(addr) : "memory");
    return v;
}
__device__ __forceinline__ void st_release_s32(unsigned addr, int v) {
    asm volatile("st.release.cta.shared.b32 [%0], %1;" :: "r"(addr), "r"(v) : "memory");
}

// ---------------------------------------------------------------------------
// Producer: UC columns per lane (register-resident seq2), every row.
// ---------------------------------------------------------------------------
template<int UC>
__device__ __forceinline__ void produce(int ustart, int bb, int lane, int wid,
                                        const float* __restrict__ seq2,
                                        unsigned s1b, unsigned ringb, unsigned sq1b,
                                        unsigned progb, unsigned pwb)
{
    unsigned long long s2r[UC][16];
    float sq2[UC];
    unsigned soff[UC];
#pragma unroll
    for (int c = 0; c < UC; ++c) {
        const int col = (ustart + c) * 32 + lane;
        const float4* v = reinterpret_cast<const float4*>(
            seq2 + (size_t)bb * M * D + (size_t)col * D);
        float acc = 0.f;
#pragma unroll
        for (int q = 0; q < 8; ++q) {
            float4 x = v[q];
            s2r[c][2 * q]     = pack2f(x.x, x.y);
            s2r[c][2 * q + 1] = pack2f(x.z, x.w);
            acc = fmaf(x.x, x.x, acc); acc = fmaf(x.y, x.y, acc);
            acc = fmaf(x.z, x.z, acc); acc = fmaf(x.w, x.w, acc);
        }
        sq2[c] = acc;
        soff[c] = (unsigned)((((col >> 4) * TSTRIDE_F) + (col & 15)) * 4);
    }

    const unsigned mypw = pwb + (unsigned)(wid * 32);

#pragma unroll 1
    for (int r = 0; r < N; ++r) {
        if (r >= RSLOTS) {
            if (ld_acquire_s32(progb) < r - LEAD) {
                while (ld_acquire_s32(progb) < r - LEAD) __nanosleep(40);
            }
        }
        const unsigned srow = s1b + (unsigned)(r * 128);
        unsigned long long acc0[UC], acc1[UC];
#pragma unroll
        for (int c = 0; c < UC; ++c) { acc0[c] = 0ull; acc1[c] = 0ull; }
#pragma unroll
        for (int q = 0; q < 8; ++q) {
            unsigned long long a0, a1;
            lds_v2u64(srow + q * 16, a0, a1);        // broadcast
#pragma unroll
            for (int c = 0; c < UC; ++c) {
                ffma2(acc0[c], a0, s2r[c][2 * q]);
                ffma2(acc1[c], a1, s2r[c][2 * q + 1]);
            }
        }
        const float sq1r = lds_f32(sq1b + (unsigned)(r * 4));
        const unsigned slot = ringb + (unsigned)((r % RSLOTS) * SLOT_F * 4);
#pragma unroll
        for (int c = 0; c < UC; ++c) {
            float e0, e1, e2, e3;
            unpack2f(acc0[c], e0, e1); unpack2f(acc1[c], e2, e3);
            float dot = (e0 + e1) + (e2 + e3);
            float dd = sq1r + sq2[c] - 2.f * dot;
            sts_f32(slot + soff[c], fast_sqrt(fmaxf(dd, 1e-12f)));
        }
        __syncwarp();
        if (lane == 0) st_release_s32(mypw, r);
    }
}

// ---------------------------------------------------------------------------
__global__ __launch_bounds__(THREADS)
void fused_dtw(const float* __restrict__ seq1, const float* __restrict__ seq2,
               float* __restrict__ out)
{
    extern __shared__ float sm[];
    const int b = blockIdx.x;
    const int tid = threadIdx.x;
    const int wid = tid >> 5;
    const int lane = tid & 31;

    const unsigned smb   = (unsigned)__cvta_generic_to_shared(sm);
    const unsigned s1b   = smb + OFF_S1 * 4;
    const unsigned ringb = smb + OFF_RING * 4;
    const unsigned sq1b  = smb + OFF_SQ1 * 4;
    const unsigned pwb   = smb + OFF_PW * 4;
    const unsigned progb = smb + OFF_PROG * 4;

    // ---- stage seq1 (64KB) via cp.async; init words ----
    const float* s1g = seq1 + (size_t)b * N * D;
    for (int c = tid; c < 512 * 8; c += THREADS) {
        int row = c >> 3, q = c & 7;
        cp_async16(s1b + (unsigned)(row * 128 + q * 16), s1g + row * 32 + q * 4);
    }
    asm volatile("cp.async.commit_group;\n" ::: "memory");
    if (tid < 8) ((int*)(sm + OFF_PW))[tid * 8] = -1;
    if (tid == 0) ((int*)(sm + OFF_PROG))[0] = -1;
    asm volatile("cp.async.wait_group 0;\n" ::: "memory");
    __syncthreads();

    for (int jj = tid; jj < 512; jj += THREADS) {
        const float* rp = sm + OFF_S1 + jj * 32;
        float acc = 0.f;
#pragma unroll
        for (int k = 0; k < 32; ++k) acc = fmaf(rp[k], rp[k], acc);
        sm[OFF_SQ1 + jj] = acc;
    }
    __syncthreads();

    if (wid == 8) {
        // =================== CONSUMER ===================
        const int t = lane;
        const float INF = INFINITY;

        float vprev[16];
#pragma unroll
        for (int k = 0; k < 16; ++k) vprev[k] = INF;
        float diag0 = (t == 0) ? 0.f : INF;
        float lastv = INF;

        // readiness = min over 7 producer words (wid 0,1,2,3,5,6,7)
        auto min7 = [&]() -> int {
            int m = ld_acquire_s32(pwb + 0 * 32);
            m = min(m, ld_acquire_s32(pwb + 1 * 32));
            m = min(m, ld_acquire_s32(pwb + 2 * 32));
            m = min(m, ld_acquire_s32(pwb + 3 * 32));
            m = min(m, ld_acquire_s32(pwb + 5 * 32));
            m = min(m, ld_acquire_s32(pwb + 6 * 32));
            m = min(m, ld_acquire_s32(pwb + 7 * 32));
            return m;
        };

        int ready = -1;
        while (ready < 1) { ready = min7(); if (ready < 1) __nanosleep(80); }

        // prefetch P (prefix sums of own 16-col slice) for steps 0 and 1
        float PA[16], PB[16];
        auto prefetchP = [&](float* P, int row) {
            const float4* cp = reinterpret_cast<const float4*>(
                sm + OFF_RING + (row % RSLOTS) * SLOT_F + t * TSTRIDE_F);
            float4 c0 = cp[0], c1 = cp[1], c2 = cp[2], c3 = cp[3];
            float c[16] = { c0.x, c0.y, c0.z, c0.w, c1.x, c1.y, c1.z, c1.w,
                            c2.x, c2.y, c2.z, c2.w, c3.x, c3.y, c3.z, c3.w };
            P[0] = c[0];
#pragma unroll
            for (int k = 1; k < 16; ++k) P[k] = P[k - 1] + c[k];
        };
        {
            int r0 = 0 - t;  r0 = min(max(r0, 0), N - 1);
            int r1 = 1 - t;  r1 = min(max(r1, 0), N - 1);
            prefetchP(PA, r0);
            prefetchP(PB, r1);
        }

        auto cstep = [&](int s, float* P) {
            float left0 = __shfl_up_sync(0xffffffffu, lastv, 1);
            if (t == 0) left0 = INF;

            const int r = s - t;
            if (r >= 0 && r < N) {
                float w[16];
                w[0] = fminf(vprev[0], diag0);
#pragma unroll
                for (int k = 1; k < 16; ++k)
                    w[k] = fminf(vprev[k], vprev[k - 1]) - P[k - 1];
#pragma unroll
                for (int k = 1; k < 16; ++k) w[k] = fminf(w[k], w[k - 1]);
#pragma unroll
                for (int k = 0; k < 16; ++k)
                    vprev[k] = P[k] + fminf(left0, w[k]);
                lastv = vprev[15];
                diag0 = left0;
            }

            if (lane == 0) st_release_s32(progb, s);

            // readiness + prefetch for step s+2 (refill same buffer)
            int ren = min(s + 2, N - 1);
            if (ready < ren) {
                do { ready = min7(); if (ready < ren) __nanosleep(60); }
                while (ready < ren);
            }
            int rn = s + 2 - t;
            rn = min(max(rn, 0), N - 1);
            prefetchP(P, rn);
        };

        // 544 steps (even; steps >= 543 are all-inactive, harmless)
        for (int s = 0; s < 544; s += 2) {
            cstep(s, PA);
            cstep(s + 1, PB);
        }

        if (t == 31) out[b] = lastv;   // D[N-1][M-1]
    } else if (wid != 4) {
        // =================== PRODUCERS ===================
        // units (32 cols each): w0:1 @0 | w1:3 @1 | w2:3 @4 | w3:3 @7 |
        //                       w5:2 @10 | w6:2 @12 | w7:2 @14   (16 total)
        if      (wid == 0) produce<1>(0,  b, lane, wid, seq2, s1b, ringb, sq1b, progb, pwb);
        else if (wid == 1) produce<3>(1,  b, lane, wid, seq2, s1b, ringb, sq1b, progb, pwb);
        else if (wid == 2) produce<3>(4,  b, lane, wid, seq2, s1b, ringb, sq1b, progb, pwb);
        else if (wid == 3) produce<3>(7,  b, lane, wid, seq2, s1b, ringb, sq1b, progb, pwb);
        else if (wid == 5) produce<2>(10, b, lane, wid, seq2, s1b, ringb, sq1b, progb, pwb);
        else if (wid == 6) produce<2>(12, b, lane, wid, seq2, s1b, ringb, sq1b, progb, pwb);
        else               produce<2>(14, b, lane, wid, seq2, s1b, ringb, sq1b, progb, pwb);
    }
    // wid == 4: idle (keeps consumer's SMSP0 light)
}

// ---------------------------------------------------------------------------
extern "C" void kernel_launch(void* const* d_in, const int* in_sizes, int n_in,
                              void* d_out, int out_size)
{
    const float* seq1 = (const float*)d_in[0];
    const float* seq2 = (const float*)d_in[1];
    float* out = (float*)d_out;

    cudaFuncSetAttribute(fused_dtw, cudaFuncAttributeMaxDynamicSharedMemorySize,
                         SMEM_BYTES);
    fused_dtw<<<B, THREADS, SMEM_BYTES>>>(seq1, seq2, out);
}